// round 5
// baseline (speedup 1.0000x reference)
#include <cuda_runtime.h>
#include <cuda_bf16.h>

#define CCONST 7.1998226
#define RPB 16        // rows per block
#define THREADS 256
#define MAXB 64

__device__ double g_sum[MAXB];           // zero-initialized at module load
__device__ unsigned int g_done = 0;      // ticket counter (auto-wraps to 0)

__global__ __launch_bounds__(THREADS)
void coulomb_fused(const float* __restrict__ dij,
                   const float* __restrict__ q,
                   float* __restrict__ out,
                   int N, int B, unsigned int totalBlocks) {
    const int b   = blockIdx.y;
    const int rg  = blockIdx.x;
    const int tid = threadIdx.x;

    const float* qb = q + (size_t)b * N;

    // fixed column ownership: 8 contiguous columns per thread, q_j in registers
    const int j0 = tid * 8;
    const float4 qa = __ldg((const float4*)(qb + j0));
    const float4 qc = __ldg((const float4*)(qb + j0 + 4));

    const int row0 = rg * RPB;
    const float* base = dij + ((size_t)b * N + row0) * (size_t)N + j0;

    float qi[RPB];
#pragma unroll
    for (int r = 0; r < RPB; r++) qi[r] = __ldg(qb + row0 + r);

    float acc0 = 0.0f, acc1 = 0.0f;

#pragma unroll
    for (int r = 0; r < RPB; r += 2) {
        // streaming loads: d_ij is read exactly once — evict-first
        float4 da0 = __ldcs((const float4*)(base + (size_t)r * N));
        float4 dc0 = __ldcs((const float4*)(base + (size_t)r * N) + 1);
        float4 da1 = __ldcs((const float4*)(base + (size_t)(r + 1) * N));
        float4 dc1 = __ldcs((const float4*)(base + (size_t)(r + 1) * N) + 1);

        float l0;
        l0  = __fdividef(qa.x, da0.x);
        l0 += __fdividef(qa.y, da0.y);
        l0 += __fdividef(qa.z, da0.z);
        l0 += __fdividef(qa.w, da0.w);
        l0 += __fdividef(qc.x, dc0.x);
        l0 += __fdividef(qc.y, dc0.y);
        l0 += __fdividef(qc.z, dc0.z);
        l0 += __fdividef(qc.w, dc0.w);
        acc0 = fmaf(qi[r], l0, acc0);

        float l1;
        l1  = __fdividef(qa.x, da1.x);
        l1 += __fdividef(qa.y, da1.y);
        l1 += __fdividef(qa.z, da1.z);
        l1 += __fdividef(qa.w, da1.w);
        l1 += __fdividef(qc.x, dc1.x);
        l1 += __fdividef(qc.y, dc1.y);
        l1 += __fdividef(qc.z, dc1.z);
        l1 += __fdividef(qc.w, dc1.w);
        acc1 = fmaf(qi[r + 1], l1, acc1);
    }

    // single fp64 promote per thread, then block reduce
    double acc = (double)acc0 + (double)acc1;

    #pragma unroll
    for (int off = 16; off; off >>= 1)
        acc += __shfl_down_sync(0xffffffffu, acc, off);

    __shared__ double sm[THREADS / 32];
    __shared__ bool is_last;
    if ((tid & 31) == 0) sm[tid >> 5] = acc;
    __syncthreads();

    if (tid < 32) {
        double v = (tid < THREADS / 32) ? sm[tid] : 0.0;
        #pragma unroll
        for (int off = 4; off; off >>= 1)
            v += __shfl_down_sync(0xffffffffu, v, off);
        if (tid == 0) {
            atomicAdd(&g_sum[b], v);
            __threadfence();
            // atomicInc wraps to 0 after totalBlocks-1 -> counter auto-resets
            unsigned int ticket = atomicInc(&g_done, totalBlocks - 1);
            is_last = (ticket == totalBlocks - 1);
        }
    }
    __syncthreads();

    if (is_last && tid < B) {
        // L2-coherent read of the accumulated total
        double total = atomicAdd(&g_sum[tid], 0.0);
        out[tid] = (float)(CCONST * total);
        g_sum[tid] = 0.0;   // reset for next graph replay
    }
}

extern "C" void kernel_launch(void* const* d_in, const int* in_sizes, int n_in,
                              void* d_out, int out_size) {
    // Identify inputs by element count: largest = d_ij [B,N,N]; q = [B,N].
    int di = 0;
    for (int i = 1; i < n_in; i++)
        if (in_sizes[i] > in_sizes[di]) di = i;

    const float* dij = (const float*)d_in[di];

    const long long B = (out_size > 0) ? out_size : 16;
    int qi = (di == 0 && n_in > 1) ? 1 : 0;
    for (int i = 0; i < n_in; i++) {
        if (i == di) continue;
        long long nq = in_sizes[i];
        long long Nc = nq / B;
        if (Nc > 0 && B * Nc * Nc == (long long)in_sizes[di]) { qi = i; break; }
    }
    const float* q = (const float*)d_in[qi];

    const int N = (int)((long long)in_sizes[qi] / B);   // 2048
    const int row_groups = N / RPB;                     // 128
    const unsigned int totalBlocks = (unsigned int)(row_groups * B);

    dim3 grid(row_groups, (unsigned)B);
    coulomb_fused<<<grid, THREADS>>>(dij, q, (float*)d_out, N, (int)B, totalBlocks);
}

// round 6
// speedup vs baseline: 1.1404x; 1.1404x over previous
#include <cuda_runtime.h>
#include <cuda_bf16.h>

#define CCONST 7.1998226
#define RPB 8          // rows per tile
#define THREADS 256
#define MAXB 64

__device__ double g_sum[MAXB];           // zero-initialized at module load
__device__ unsigned int g_done = 0;      // ticket counter (auto-wraps)

__global__ __launch_bounds__(THREADS, 4)
void coulomb_persist(const float* __restrict__ dij,
                     const float* __restrict__ q,
                     float* __restrict__ out,
                     int N, int B, unsigned int totalBlocks) {
    const int b   = blockIdx.y;
    const int bpb = gridDim.x;           // blocks per batch
    const int tid = threadIdx.x;
    const int Tb  = N / RPB;             // tiles (row groups) per batch

    const float* qb = q + (size_t)b * N;

    // fixed column ownership for the whole block lifetime
    const int j0 = tid * 8;
    const float4 qa = __ldg((const float4*)(qb + j0));
    const float4 qc = __ldg((const float4*)(qb + j0 + 4));

    double acc = 0.0;

    for (int rg = blockIdx.x; rg < Tb; rg += bpb) {
        const int row0 = rg * RPB;
        const float* base = dij + ((size_t)b * N + row0) * (size_t)N + j0;

        float qi[RPB];
#pragma unroll
        for (int r = 0; r < RPB; r++) qi[r] = __ldg(qb + row0 + r);

        float acc0 = 0.0f, acc1 = 0.0f;

#pragma unroll
        for (int h = 0; h < RPB; h += 4) {
            // front-batch 8 independent float4 loads (4 rows x 2)
            float4 da0 = __ldcs((const float4*)(base + (size_t)(h + 0) * N));
            float4 dc0 = __ldcs((const float4*)(base + (size_t)(h + 0) * N) + 1);
            float4 da1 = __ldcs((const float4*)(base + (size_t)(h + 1) * N));
            float4 dc1 = __ldcs((const float4*)(base + (size_t)(h + 1) * N) + 1);
            float4 da2 = __ldcs((const float4*)(base + (size_t)(h + 2) * N));
            float4 dc2 = __ldcs((const float4*)(base + (size_t)(h + 2) * N) + 1);
            float4 da3 = __ldcs((const float4*)(base + (size_t)(h + 3) * N));
            float4 dc3 = __ldcs((const float4*)(base + (size_t)(h + 3) * N) + 1);

            float l0 = __fdividef(qa.x, da0.x) + __fdividef(qa.y, da0.y)
                     + __fdividef(qa.z, da0.z) + __fdividef(qa.w, da0.w)
                     + __fdividef(qc.x, dc0.x) + __fdividef(qc.y, dc0.y)
                     + __fdividef(qc.z, dc0.z) + __fdividef(qc.w, dc0.w);
            acc0 = fmaf(qi[h + 0], l0, acc0);

            float l1 = __fdividef(qa.x, da1.x) + __fdividef(qa.y, da1.y)
                     + __fdividef(qa.z, da1.z) + __fdividef(qa.w, da1.w)
                     + __fdividef(qc.x, dc1.x) + __fdividef(qc.y, dc1.y)
                     + __fdividef(qc.z, dc1.z) + __fdividef(qc.w, dc1.w);
            acc1 = fmaf(qi[h + 1], l1, acc1);

            float l2 = __fdividef(qa.x, da2.x) + __fdividef(qa.y, da2.y)
                     + __fdividef(qa.z, da2.z) + __fdividef(qa.w, da2.w)
                     + __fdividef(qc.x, dc2.x) + __fdividef(qc.y, dc2.y)
                     + __fdividef(qc.z, dc2.z) + __fdividef(qc.w, dc2.w);
            acc0 = fmaf(qi[h + 2], l2, acc0);

            float l3 = __fdividef(qa.x, da3.x) + __fdividef(qa.y, da3.y)
                     + __fdividef(qa.z, da3.z) + __fdividef(qa.w, da3.w)
                     + __fdividef(qc.x, dc3.x) + __fdividef(qc.y, dc3.y)
                     + __fdividef(qc.z, dc3.z) + __fdividef(qc.w, dc3.w);
            acc1 = fmaf(qi[h + 3], l3, acc1);
        }

        // promote to fp64 once per tile
        acc += (double)acc0 + (double)acc1;
    }

    // block reduce (fp64)
    #pragma unroll
    for (int off = 16; off; off >>= 1)
        acc += __shfl_down_sync(0xffffffffu, acc, off);

    __shared__ double sm[THREADS / 32];
    __shared__ bool is_last;
    if ((tid & 31) == 0) sm[tid >> 5] = acc;
    __syncthreads();

    if (tid < 32) {
        double v = (tid < THREADS / 32) ? sm[tid] : 0.0;
        #pragma unroll
        for (int off = 4; off; off >>= 1)
            v += __shfl_down_sync(0xffffffffu, v, off);
        if (tid == 0) {
            atomicAdd(&g_sum[b], v);
            __threadfence();
            unsigned int ticket = atomicInc(&g_done, totalBlocks - 1);
            is_last = (ticket == totalBlocks - 1);
        }
    }
    __syncthreads();

    if (is_last && tid < B) {
        double total = atomicAdd(&g_sum[tid], 0.0);   // coherent read
        out[tid] = (float)(CCONST * total);
        g_sum[tid] = 0.0;                             // reset for next replay
    }
}

extern "C" void kernel_launch(void* const* d_in, const int* in_sizes, int n_in,
                              void* d_out, int out_size) {
    // Identify inputs by element count: largest = d_ij [B,N,N]; q = [B,N].
    int di = 0;
    for (int i = 1; i < n_in; i++)
        if (in_sizes[i] > in_sizes[di]) di = i;
    const float* dij = (const float*)d_in[di];

    const long long B = (out_size > 0) ? out_size : 16;
    int qi = (di == 0 && n_in > 1) ? 1 : 0;
    for (int i = 0; i < n_in; i++) {
        if (i == di) continue;
        long long nq = in_sizes[i];
        long long Nc = nq / B;
        if (Nc > 0 && B * Nc * Nc == (long long)in_sizes[di]) { qi = i; break; }
    }
    const float* q = (const float*)d_in[qi];

    const int N = (int)((long long)in_sizes[qi] / B);   // 2048

    int sm_count = 148;
    cudaDeviceGetAttribute(&sm_count, cudaDevAttrMultiProcessorCount, 0);

    // blocks per batch: ~4 CTAs/SM total, exactly divisible by B
    int bpb = (sm_count * 4) / (int)B;                  // 152*4/16 = 38
    if (bpb < 1) bpb = 1;
    const int Tb = N / RPB;                             // 256 tiles per batch
    if (bpb > Tb) bpb = Tb;

    const unsigned int totalBlocks = (unsigned int)(bpb * B);
    dim3 grid(bpb, (unsigned)B);
    coulomb_persist<<<grid, THREADS>>>(dij, q, (float*)d_out, N, (int)B, totalBlocks);
}